// round 1
// baseline (speedup 1.0000x reference)
#include <cuda_runtime.h>

#define NMAX 20000
#define EMAX 320000
#define D 256
#define NC 512   // self 256 cols | neigh 256 cols

// ---------------- scratch (__device__ globals: no allocation allowed) ----------
__device__ __align__(16) float g_Xf[NMAX * D];            // normalized, sign-folded features
__device__ float g_habs[NMAX];                            // |h|
__device__ __align__(16) float g_C[(size_t)NMAX * NC];    // [Sn | Nn] after norm pass
__device__ __align__(16) float g_Wcat[D * NC];            // B matrix: [k][j]
__device__ int g_deg[NMAX];
__device__ int g_off[NMAX + 1];
__device__ int g_cur[NMAX];
__device__ int g_bucket[EMAX];

__device__ __forceinline__ float warp_sum(float v) {
#pragma unroll
    for (int o = 16; o > 0; o >>= 1) v += __shfl_xor_sync(0xffffffffu, v, o);
    return v;
}

// ---------------- 1. per-node input normalization (1 warp / node) --------------
__global__ void prep_kernel(const float* __restrict__ x, int N) {
    int gid = blockIdx.x * blockDim.x + threadIdx.x;
    if (gid < N) g_deg[gid] = 0;   // zero degree counters here too
    int w = gid >> 5;
    int lane = threadIdx.x & 31;
    if (w >= N) return;
    const float* xr = x + (size_t)w * (D + 1);
    float v[8];
    float ss = 0.f;
    bool nz = false;
#pragma unroll
    for (int k = 0; k < 8; k++) {
        float t = xr[k * 32 + lane];
        v[k] = t;
        ss += t * t;
        nz |= (t != 0.f);
    }
    unsigned m = __ballot_sync(0xffffffffu, nz);
    ss = warp_sum(ss);
    float h = xr[D];
    float s0 = (h < 0.f) ? -1.f : 1.f;
    float scale;
    if (m == 0u) {                        // all-zero feature row -> ones
#pragma unroll
        for (int k = 0; k < 8; k++) v[k] = 1.f;
        scale = s0 * (1.f / 16.f);
    } else {
        scale = s0 / fmaxf(sqrtf(ss), 1e-8f);
    }
#pragma unroll
    for (int k = 0; k < 8; k++) g_Xf[(size_t)w * D + k * 32 + lane] = v[k] * scale;
    if (lane == 0) g_habs[w] = h * s0;
}

// ---------------- 2. pack Wcat[k][j] = (j<256 ? Ws[j][k] : Wn[j-256][k]) -------
__global__ void wcat_kernel(const float* __restrict__ Ws, const float* __restrict__ Wn) {
    int idx = blockIdx.x * blockDim.x + threadIdx.x;
    if (idx < D * NC) {
        int k = idx / NC, j = idx % NC;
        g_Wcat[idx] = (j < D) ? Ws[j * D + k] : Wn[(j - D) * D + k];
    }
}

// ---------------- 3. count edges per destination row ---------------------------
__global__ void count_kernel(const int* __restrict__ ei, int E) {
    int e = blockIdx.x * blockDim.x + threadIdx.x;
    if (e < E) atomicAdd(&g_deg[ei[e]], 1);
}

// ---------------- 4. single-block exclusive scan over degrees ------------------
__global__ void scan_kernel(int N) {
    __shared__ int sh[512];
    int t = threadIdx.x;
    int chunk = (N + 511) / 512;
    int base = t * chunk;
    int s = 0;
    for (int i = 0; i < chunk; i++) {
        int idx = base + i;
        if (idx < N) s += g_deg[idx];
    }
    sh[t] = s;
    __syncthreads();
    for (int o = 1; o < 512; o <<= 1) {
        int v = (t >= o) ? sh[t - o] : 0;
        __syncthreads();
        sh[t] += v;
        __syncthreads();
    }
    int run = sh[t] - s;  // exclusive prefix of this thread's chunk
    for (int i = 0; i < chunk; i++) {
        int idx = base + i;
        if (idx < N) {
            g_off[idx] = run;
            g_cur[idx] = run;
            run += g_deg[idx];
        }
    }
    if (t == 511) g_off[N] = sh[511];
}

// ---------------- 5. bucket edge sources by destination ------------------------
__global__ void fill_kernel(const int* __restrict__ ei, int E) {
    int e = blockIdx.x * blockDim.x + threadIdx.x;
    if (e < E) {
        int r = ei[e];
        int c = ei[E + e];
        int p = atomicAdd(&g_cur[r], 1);
        g_bucket[p] = c;
    }
}

// ---------------- 6. SGEMM: C[N x 512] = Xf[N x 256] @ Wcat[256 x 512] ---------
#define BM 128
#define BN 128
#define BK 16
__global__ __launch_bounds__(256, 2) void gemm_kernel(int M) {
    __shared__ float As[BK][BM + 4];
    __shared__ float Bs[BK][BN];
    int tid = threadIdx.x;
    int tx = tid & 15, ty = tid >> 4;
    int row0 = blockIdx.x * BM;
    int col0 = blockIdx.y * BN;
    float acc[8][8] = {};
    int a_r = tid >> 2;   // 0..63
    int a_c4 = tid & 3;   // float4 within 16 k
    int b_k = tid >> 5;   // 0..7
    int b_n4 = tid & 31;  // float4 cols

    for (int k0 = 0; k0 < D; k0 += BK) {
#pragma unroll
        for (int rr = 0; rr < 2; rr++) {
            int r = a_r + rr * 64;
            int gr = row0 + r;
            float4 av = (gr < M)
                ? *(const float4*)(g_Xf + (size_t)gr * D + k0 + a_c4 * 4)
                : make_float4(0.f, 0.f, 0.f, 0.f);
            As[a_c4 * 4 + 0][r] = av.x;
            As[a_c4 * 4 + 1][r] = av.y;
            As[a_c4 * 4 + 2][r] = av.z;
            As[a_c4 * 4 + 3][r] = av.w;
        }
#pragma unroll
        for (int kk = 0; kk < 2; kk++) {
            int k = b_k + kk * 8;
            *(float4*)&Bs[k][b_n4 * 4] =
                *(const float4*)(g_Wcat + (size_t)(k0 + k) * NC + col0 + b_n4 * 4);
        }
        __syncthreads();
#pragma unroll
        for (int k = 0; k < BK; k++) {
            float a[8], b[8];
#pragma unroll
            for (int i = 0; i < 8; i++) a[i] = As[k][ty * 8 + i];
#pragma unroll
            for (int j = 0; j < 8; j++) b[j] = Bs[k][tx * 8 + j];
#pragma unroll
            for (int i = 0; i < 8; i++)
#pragma unroll
                for (int j = 0; j < 8; j++) acc[i][j] += a[i] * b[j];
        }
        __syncthreads();
    }
#pragma unroll
    for (int i = 0; i < 8; i++) {
        int gr = row0 + ty * 8 + i;
        if (gr < M) {
            float* Crow = g_C + (size_t)gr * NC + col0 + tx * 8;
#pragma unroll
            for (int j = 0; j < 8; j++) Crow[j] = acc[i][j];
        }
    }
}

// ---------------- 7. row-normalize each 256-wide half of C ---------------------
__global__ void norm_kernel(int N2) {
    int w = (blockIdx.x * blockDim.x + threadIdx.x) >> 5;
    int lane = threadIdx.x & 31;
    if (w >= N2) return;
    float* p = g_C + (size_t)w * D;
    float v[8];
    float ss = 0.f;
#pragma unroll
    for (int k = 0; k < 8; k++) {
        float t = p[k * 32 + lane];
        v[k] = t;
        ss += t * t;
    }
    ss = warp_sum(ss);
    if (ss == 0.f) {
#pragma unroll
        for (int k = 0; k < 8; k++) p[k * 32 + lane] = 0.0625f;
    } else {
        float inv = 1.f / sqrtf(ss);
#pragma unroll
        for (int k = 0; k < 8; k++) p[k * 32 + lane] = v[k] * inv;
    }
}

// ---------------- 8. aggregation + blend + final normalize (1 warp / node) -----
__global__ void agg_kernel(float* __restrict__ out, int N) {
    int w = (blockIdx.x * blockDim.x + threadIdx.x) >> 5;
    int lane = threadIdx.x & 31;
    if (w >= N) return;
    int beg = g_off[w], end = g_off[w + 1];
    float acc[8] = {0.f, 0.f, 0.f, 0.f, 0.f, 0.f, 0.f, 0.f};
    float acch = 0.f;
    for (int e = beg; e < end; e++) {
        int c = g_bucket[e];
        const float* p = g_C + (size_t)c * NC + D;  // neighbor-transform half
#pragma unroll
        for (int k = 0; k < 8; k++) acc[k] += p[k * 32 + lane];
        acch += g_habs[c];
    }
    float ss = 0.f;
#pragma unroll
    for (int k = 0; k < 8; k++) ss += acc[k] * acc[k];
    ss = warp_sum(ss);
    float p2[8];
    if (ss == 0.f) {
#pragma unroll
        for (int k = 0; k < 8; k++) p2[k] = 0.0625f;
    } else {
        float inv = 1.f / sqrtf(ss);
#pragma unroll
        for (int k = 0; k < 8; k++) p2[k] = acc[k] * inv;
    }
    float p2h = 1.f + acch;
    const float t = 0.5f / (1.0f - 0.5f + 1e-8f);  // == 1.0f in fp32, same as ref
    const float* srow = g_C + (size_t)w * NC;       // self-transform half
    float av[8];
    float ss2 = 0.f;
#pragma unroll
    for (int k = 0; k < 8; k++) {
        float a = srow[k * 32 + lane] * t + p2[k];
        av[k] = a;
        ss2 += a * a;
    }
    ss2 = warp_sum(ss2);
    float* orow = out + (size_t)w * (D + 1);
    if (ss2 == 0.f) {
#pragma unroll
        for (int k = 0; k < 8; k++) orow[k * 32 + lane] = 0.0625f;
    } else {
        float inv = 1.f / sqrtf(ss2);
#pragma unroll
        for (int k = 0; k < 8; k++) orow[k * 32 + lane] = av[k] * inv;
    }
    if (lane == 0) {
        float p1h = g_habs[w];
        orow[D] = (p1h * t + p2h) / (t + 1.0f);
    }
}

// ---------------- launch --------------------------------------------------------
extern "C" void kernel_launch(void* const* d_in, const int* in_sizes, int n_in,
                              void* d_out, int out_size) {
    const float* x  = (const float*)d_in[0];
    const float* Ws = (const float*)d_in[1];
    const float* Wn = (const float*)d_in[2];
    const int*   ei = (const int*)d_in[3];
    int N = in_sizes[0] / (D + 1);
    if (N > NMAX) N = NMAX;
    int E = in_sizes[3] / 2;
    if (E > EMAX) E = EMAX;
    float* out = (float*)d_out;

    int warpBlocks = (N * 32 + 255) / 256;
    prep_kernel<<<warpBlocks, 256>>>(x, N);
    wcat_kernel<<<(D * NC + 255) / 256, 256>>>(Ws, Wn);
    count_kernel<<<(E + 255) / 256, 256>>>(ei, E);
    scan_kernel<<<1, 512>>>(N);
    fill_kernel<<<(E + 255) / 256, 256>>>(ei, E);
    dim3 gg((N + BM - 1) / BM, NC / BN);
    gemm_kernel<<<gg, 256>>>(N);
    norm_kernel<<<(2 * N * 32 + 255) / 256, 256>>>(2 * N);
    agg_kernel<<<warpBlocks, 256>>>(out, N);
}

// round 4
// speedup vs baseline: 1.4487x; 1.4487x over previous
#include <cuda_runtime.h>
#include <cuda_bf16.h>
#include <mma.h>
#include <cstdint>

using namespace nvcuda;

#define NMAX 20000
#define EMAX 320000
#define D 256
#define NC 512   // self 256 cols | neigh 256 cols

// ---------------- scratch (__device__ globals) ----------------------------------
__device__ __align__(16) __nv_bfloat16 g_Xhi[(size_t)NMAX * D];
__device__ __align__(16) __nv_bfloat16 g_Xlo[(size_t)NMAX * D];
__device__ __align__(16) __nv_bfloat16 g_Whi[NC * D];   // [n][k], K-major
__device__ __align__(16) __nv_bfloat16 g_Wlo[NC * D];
__device__ __align__(16) float g_C[(size_t)(NMAX + 128) * NC];  // padded for tile OOB
__device__ float g_habs[NMAX];
__device__ int g_deg[NMAX];
__device__ int g_off[NMAX + 1];
__device__ int g_cur[NMAX];
__device__ int g_bucket[EMAX];
__device__ int g_bsum[160];
__device__ int g_bpre[160];

__device__ __forceinline__ float warp_sum(float v) {
#pragma unroll
    for (int o = 16; o > 0; o >>= 1) v += __shfl_xor_sync(0xffffffffu, v, o);
    return v;
}

// ---------------- 1. per-node input normalize + bf16 hi/lo split ----------------
__global__ void prep_kernel(const float* __restrict__ x, int N) {
    int gid = blockIdx.x * blockDim.x + threadIdx.x;
    if (gid < N) g_deg[gid] = 0;
    int w = gid >> 5;
    int lane = threadIdx.x & 31;
    if (w >= N) return;
    const float* xr = x + (size_t)w * (D + 1);
    float v[8];
    float ss = 0.f;
    bool nz = false;
#pragma unroll
    for (int k = 0; k < 8; k++) {
        float t = xr[k * 32 + lane];
        v[k] = t; ss += t * t; nz |= (t != 0.f);
    }
    unsigned m = __ballot_sync(0xffffffffu, nz);
    ss = warp_sum(ss);
    float h = xr[D];
    float s0 = (h < 0.f) ? -1.f : 1.f;
    float scale;
    if (m == 0u) {
#pragma unroll
        for (int k = 0; k < 8; k++) v[k] = 1.f;
        scale = s0 * (1.f / 16.f);
    } else {
        scale = s0 / fmaxf(sqrtf(ss), 1e-8f);
    }
#pragma unroll
    for (int k = 0; k < 8; k++) {
        float val = v[k] * scale;
        __nv_bfloat16 hi = __float2bfloat16_rn(val);
        float lo = val - __bfloat162float(hi);
        size_t idx = (size_t)w * D + k * 32 + lane;
        g_Xhi[idx] = hi;
        g_Xlo[idx] = __float2bfloat16_rn(lo);
    }
    if (lane == 0) g_habs[w] = h * s0;
}

// ---------------- 2. W concat rows + bf16 hi/lo split (K-major) -----------------
__global__ void wsplit_kernel(const float* __restrict__ Ws, const float* __restrict__ Wn) {
    int idx = blockIdx.x * blockDim.x + threadIdx.x;
    if (idx >= NC * D) return;
    int j = idx / D, k = idx % D;
    float w = (j < D) ? Ws[j * D + k] : Wn[(j - D) * D + k];
    __nv_bfloat16 hi = __float2bfloat16_rn(w);
    g_Whi[idx] = hi;
    g_Wlo[idx] = __float2bfloat16_rn(w - __bfloat162float(hi));
}

// ---------------- 3. count edges per destination --------------------------------
__global__ void count_kernel(const int* __restrict__ ei, int E) {
    int e = blockIdx.x * blockDim.x + threadIdx.x;
    if (e < E) atomicAdd(&g_deg[ei[e]], 1);
}

// ---------------- 4a/b/c. parallel exclusive scan -------------------------------
__global__ void scan1_kernel(int N) {
    __shared__ int sh[256];
    int t = threadIdx.x;
    int i = blockIdx.x * 256 + t;
    sh[t] = (i < N) ? g_deg[i] : 0;
    __syncthreads();
#pragma unroll
    for (int o = 128; o > 0; o >>= 1) {
        if (t < o) sh[t] += sh[t + o];
        __syncthreads();
    }
    if (t == 0) g_bsum[blockIdx.x] = sh[0];
}
__global__ void scan2_kernel(int NB, int N) {
    __shared__ int sh[160];
    int t = threadIdx.x;
    int v = (t < NB) ? g_bsum[t] : 0;
    sh[t] = v;
    __syncthreads();
    for (int o = 1; o < 160; o <<= 1) {
        int u = (t >= o) ? sh[t - o] : 0;
        __syncthreads();
        sh[t] += u;
        __syncthreads();
    }
    if (t < NB) g_bpre[t] = sh[t] - v;
    if (t == NB - 1) g_off[N] = sh[t];
}
__global__ void scan3_kernel(int N) {
    __shared__ int sh[256];
    int t = threadIdx.x;
    int i = blockIdx.x * 256 + t;
    int v = (i < N) ? g_deg[i] : 0;
    sh[t] = v;
    __syncthreads();
#pragma unroll
    for (int o = 1; o < 256; o <<= 1) {
        int u = (t >= o) ? sh[t - o] : 0;
        __syncthreads();
        sh[t] += u;
        __syncthreads();
    }
    if (i < N) {
        int e = sh[t] - v + g_bpre[blockIdx.x];
        g_off[i] = e;
        g_cur[i] = e;
    }
}

// ---------------- 5. bucket edge sources by destination -------------------------
__global__ void fill_kernel(const int* __restrict__ ei, int E) {
    int e = blockIdx.x * blockDim.x + threadIdx.x;
    if (e < E) {
        int r = ei[e];
        int c = ei[E + e];
        int p = atomicAdd(&g_cur[r], 1);
        g_bucket[p] = c;
    }
}

// ---------------- 6. WMMA bf16 3-term split GEMM --------------------------------
// C[m][j] = sum_k X[m][k]*Wcat[j][k] (Wcat K-major). CTA tile 128x128, 8 warps,
// warp tile 64x32 (4x2 frags). K-chunk 32 in smem, ldm=40 (80B rows, 16B aligned).
#define GLDM 40
__global__ __launch_bounds__(256) void gemm_wmma_kernel(int M) {
    __shared__ __nv_bfloat16 AsHi[128 * GLDM];
    __shared__ __nv_bfloat16 AsLo[128 * GLDM];
    __shared__ __nv_bfloat16 BsHi[128 * GLDM];
    __shared__ __nv_bfloat16 BsLo[128 * GLDM];

    int tid = threadIdx.x;
    int wid = tid >> 5;
    int warp_row = wid >> 2;      // 0..1
    int warp_col = wid & 3;       // 0..3
    int row0 = blockIdx.x * 128;
    int j0 = blockIdx.y * 128;

    wmma::fragment<wmma::accumulator, 16, 16, 16, float> acc[4][2];
#pragma unroll
    for (int i = 0; i < 4; i++)
#pragma unroll
        for (int j = 0; j < 2; j++) wmma::fill_fragment(acc[i][j], 0.f);

    int lrow = tid >> 1;          // 0..127
    int seg = tid & 1;            // 0..1 (16 bf16 each)
    bool avalid = (row0 + lrow) < M;
    const uint4 z4 = make_uint4(0, 0, 0, 0);

    for (int kc = 0; kc < D; kc += 32) {
        __syncthreads();
        // A tile: rows row0+lrow, cols kc+seg*16 .. +16
        {
            const uint4* ph = (const uint4*)(g_Xhi + (size_t)(row0 + lrow) * D + kc + seg * 16);
            const uint4* pl = (const uint4*)(g_Xlo + (size_t)(row0 + lrow) * D + kc + seg * 16);
            uint4 h0 = avalid ? ph[0] : z4, h1 = avalid ? ph[1] : z4;
            uint4 l0 = avalid ? pl[0] : z4, l1 = avalid ? pl[1] : z4;
            uint4* dh = (uint4*)(AsHi + lrow * GLDM + seg * 16);
            uint4* dl = (uint4*)(AsLo + lrow * GLDM + seg * 16);
            dh[0] = h0; dh[1] = h1;
            dl[0] = l0; dl[1] = l1;
        }
        // B tile: W rows j0+lrow, cols kc+seg*16 .. +16
        {
            const uint4* ph = (const uint4*)(g_Whi + (size_t)(j0 + lrow) * D + kc + seg * 16);
            const uint4* pl = (const uint4*)(g_Wlo + (size_t)(j0 + lrow) * D + kc + seg * 16);
            uint4 h0 = ph[0], h1 = ph[1];
            uint4 l0 = pl[0], l1 = pl[1];
            uint4* dh = (uint4*)(BsHi + lrow * GLDM + seg * 16);
            uint4* dl = (uint4*)(BsLo + lrow * GLDM + seg * 16);
            dh[0] = h0; dh[1] = h1;
            dl[0] = l0; dl[1] = l1;
        }
        __syncthreads();

#pragma unroll
        for (int ks = 0; ks < 2; ks++) {
            wmma::fragment<wmma::matrix_a, 16, 16, 16, __nv_bfloat16, wmma::row_major> aHi[4], aLo[4];
            wmma::fragment<wmma::matrix_b, 16, 16, 16, __nv_bfloat16, wmma::col_major> bHi[2], bLo[2];
#pragma unroll
            for (int i = 0; i < 4; i++) {
                const __nv_bfloat16* pa = AsHi + (warp_row * 64 + i * 16) * GLDM + ks * 16;
                wmma::load_matrix_sync(aHi[i], pa, GLDM);
                wmma::load_matrix_sync(aLo[i], pa + (AsLo - AsHi), GLDM);
            }
#pragma unroll
            for (int j = 0; j < 2; j++) {
                const __nv_bfloat16* pb = BsHi + (warp_col * 32 + j * 16) * GLDM + ks * 16;
                wmma::load_matrix_sync(bHi[j], pb, GLDM);
                wmma::load_matrix_sync(bLo[j], pb + (BsLo - BsHi), GLDM);
            }
#pragma unroll
            for (int i = 0; i < 4; i++)
#pragma unroll
                for (int j = 0; j < 2; j++) {
                    wmma::mma_sync(acc[i][j], aHi[i], bHi[j], acc[i][j]);
                    wmma::mma_sync(acc[i][j], aHi[i], bLo[j], acc[i][j]);
                    wmma::mma_sync(acc[i][j], aLo[i], bHi[j], acc[i][j]);
                }
        }
    }

    // epilogue (g_C has 128 pad rows, so full-frag stores at the M edge are safe)
#pragma unroll
    for (int i = 0; i < 4; i++) {
        int r = row0 + warp_row * 64 + i * 16;
        if (r < M + 127) {
#pragma unroll
            for (int j = 0; j < 2; j++) {
                float* cp = g_C + (size_t)r * NC + j0 + warp_col * 32 + j * 16;
                wmma::store_matrix_sync(cp, acc[i][j], NC, wmma::mem_row_major);
            }
        }
    }
}

// ---------------- 7. row-normalize each 256-wide half of C ----------------------
__global__ void norm_kernel(int N2) {
    int w = (blockIdx.x * blockDim.x + threadIdx.x) >> 5;
    int lane = threadIdx.x & 31;
    if (w >= N2) return;
    float* p = g_C + (size_t)w * D;
    float v[8];
    float ss = 0.f;
#pragma unroll
    for (int k = 0; k < 8; k++) {
        float t = p[k * 32 + lane];
        v[k] = t;
        ss += t * t;
    }
    ss = warp_sum(ss);
    if (ss == 0.f) {
#pragma unroll
        for (int k = 0; k < 8; k++) p[k * 32 + lane] = 0.0625f;
    } else {
        float inv = 1.f / fmaxf(sqrtf(ss), 1e-8f);
#pragma unroll
        for (int k = 0; k < 8; k++) p[k * 32 + lane] = v[k] * inv;
    }
}

// ---------------- 8. aggregation + blend + final normalize (1 warp / node) ------
__global__ void agg_kernel(float* __restrict__ out, int N) {
    int w = (blockIdx.x * blockDim.x + threadIdx.x) >> 5;
    int lane = threadIdx.x & 31;
    if (w >= N) return;
    int beg = g_off[w], end = g_off[w + 1];
    float acc[8] = {0.f, 0.f, 0.f, 0.f, 0.f, 0.f, 0.f, 0.f};
    float acch = 0.f;
    for (int e = beg; e < end; e++) {
        int c = g_bucket[e];
        const float* p = g_C + (size_t)c * NC + D;
#pragma unroll
        for (int k = 0; k < 8; k++) acc[k] += p[k * 32 + lane];
        acch += g_habs[c];
    }
    float ss = 0.f;
#pragma unroll
    for (int k = 0; k < 8; k++) ss += acc[k] * acc[k];
    ss = warp_sum(ss);
    float p2[8];
    if (ss == 0.f) {
#pragma unroll
        for (int k = 0; k < 8; k++) p2[k] = 0.0625f;
    } else {
        float iv = 1.f / fmaxf(sqrtf(ss), 1e-8f);
#pragma unroll
        for (int k = 0; k < 8; k++) p2[k] = acc[k] * iv;
    }
    float p2h = 1.f + acch;
    const float t = 0.5f / (1.0f - 0.5f + 1e-8f);  // == 1.0f in fp32, as reference
    const float* srow = g_C + (size_t)w * NC;
    float avv[8];
    float ss2 = 0.f;
#pragma unroll
    for (int k = 0; k < 8; k++) {
        float a = srow[k * 32 + lane] * t + p2[k];
        avv[k] = a;
        ss2 += a * a;
    }
    ss2 = warp_sum(ss2);
    float* orow = out + (size_t)w * (D + 1);
    if (ss2 == 0.f) {
#pragma unroll
        for (int k = 0; k < 8; k++) orow[k * 32 + lane] = 0.0625f;
    } else {
        float iv = 1.f / fmaxf(sqrtf(ss2), 1e-8f);
#pragma unroll
        for (int k = 0; k < 8; k++) orow[k * 32 + lane] = avv[k] * iv;
    }
    if (lane == 0) {
        float p1h = g_habs[w];
        orow[D] = (p1h * t + p2h) / (t + 1.0f);
    }
}

// ---------------- launch --------------------------------------------------------
extern "C" void kernel_launch(void* const* d_in, const int* in_sizes, int n_in,
                              void* d_out, int out_size) {
    const float* x  = (const float*)d_in[0];
    const float* Ws = (const float*)d_in[1];
    const float* Wn = (const float*)d_in[2];
    const int*   ei = (const int*)d_in[3];
    int N = in_sizes[0] / (D + 1);
    if (N > NMAX) N = NMAX;
    int E = in_sizes[3] / 2;
    if (E > EMAX) E = EMAX;
    float* out = (float*)d_out;

    int warpBlocks = (N * 32 + 255) / 256;
    int NB = (N + 255) / 256;
    prep_kernel<<<warpBlocks, 256>>>(x, N);
    wsplit_kernel<<<(NC * D + 255) / 256, 256>>>(Ws, Wn);
    count_kernel<<<(E + 255) / 256, 256>>>(ei, E);
    scan1_kernel<<<NB, 256>>>(N);
    scan2_kernel<<<1, 160>>>(NB, N);
    scan3_kernel<<<NB, 256>>>(N);
    fill_kernel<<<(E + 255) / 256, 256>>>(ei, E);
    dim3 gg((N + 127) / 128, NC / 128);
    gemm_wmma_kernel<<<gg, 256>>>(N);
    norm_kernel<<<(2 * N * 32 + 255) / 256, 256>>>(2 * N);
    agg_kernel<<<warpBlocks, 256>>>(out, N);
}

// round 9
// speedup vs baseline: 1.7100x; 1.1803x over previous
#include <cuda_runtime.h>
#include <cuda_bf16.h>
#include <mma.h>
#include <cstdint>

using namespace nvcuda;

#define NMAX 20000
#define XPAD 20096           // NMAX rounded up to 128-row tiles
#define EMAX 320000
#define D 256
#define NC 512   // self 256 cols | neigh 256 cols

// ---------------- scratch (__device__ globals) ----------------------------------
__device__ __align__(16) __nv_bfloat16 g_Xhi[(size_t)XPAD * D];
__device__ __align__(16) __nv_bfloat16 g_Xlo[(size_t)XPAD * D];
__device__ __align__(16) __nv_bfloat16 g_Whi[NC * D];   // [n][k], K-major
__device__ __align__(16) __nv_bfloat16 g_Wlo[NC * D];
__device__ __align__(16) float g_C[(size_t)(XPAD + 128) * NC];  // padded for tile OOB
__device__ float g_habs[NMAX];
__device__ int g_deg[NMAX];
__device__ int g_off[NMAX + 1];
__device__ int g_cur[NMAX];
__device__ int g_bucket[EMAX];
__device__ int g_bsum[160];
__device__ int g_bpre[160];

__device__ __forceinline__ float warp_sum(float v) {
#pragma unroll
    for (int o = 16; o > 0; o >>= 1) v += __shfl_xor_sync(0xffffffffu, v, o);
    return v;
}
__device__ __forceinline__ uint32_t smem_u32(const void* p) {
    uint32_t a;
    asm("{ .reg .u64 t; cvta.to.shared.u64 t, %1; cvt.u32.u64 %0, t; }" : "=r"(a) : "l"(p));
    return a;
}
#define CP_ASYNC16(dst, src) \
    asm volatile("cp.async.cg.shared.global [%0], [%1], 16;" :: "r"(dst), "l"(src))
#define CP_COMMIT() asm volatile("cp.async.commit_group;" ::: "memory")
#define CP_WAIT(n)  asm volatile("cp.async.wait_group %0;" :: "n"(n) : "memory")

// ---------------- 1. per-node input normalize + bf16 hi/lo split ----------------
__global__ void prep_kernel(const float* __restrict__ x, int N) {
    int gid = blockIdx.x * blockDim.x + threadIdx.x;
    if (gid < N) g_deg[gid] = 0;
    int w = gid >> 5;
    int lane = threadIdx.x & 31;
    if (w >= N) return;
    const float* xr = x + (size_t)w * (D + 1);
    float v[8];
    float ss = 0.f;
    bool nz = false;
#pragma unroll
    for (int k = 0; k < 8; k++) {
        float t = xr[k * 32 + lane];
        v[k] = t; ss += t * t; nz |= (t != 0.f);
    }
    unsigned m = __ballot_sync(0xffffffffu, nz);
    ss = warp_sum(ss);
    float h = xr[D];
    float s0 = (h < 0.f) ? -1.f : 1.f;
    float scale;
    if (m == 0u) {
#pragma unroll
        for (int k = 0; k < 8; k++) v[k] = 1.f;
        scale = s0 * (1.f / 16.f);
    } else {
        scale = s0 / fmaxf(sqrtf(ss), 1e-8f);
    }
#pragma unroll
    for (int k = 0; k < 8; k++) {
        float val = v[k] * scale;
        __nv_bfloat16 hi = __float2bfloat16_rn(val);
        float lo = val - __bfloat162float(hi);
        size_t idx = (size_t)w * D + k * 32 + lane;
        g_Xhi[idx] = hi;
        g_Xlo[idx] = __float2bfloat16_rn(lo);
    }
    if (lane == 0) g_habs[w] = h * s0;
}

// ---------------- 2. W concat rows + bf16 hi/lo split (K-major) -----------------
__global__ void wsplit_kernel(const float* __restrict__ Ws, const float* __restrict__ Wn) {
    int idx = blockIdx.x * blockDim.x + threadIdx.x;
    if (idx >= NC * D) return;
    int j = idx / D, k = idx % D;
    float w = (j < D) ? Ws[j * D + k] : Wn[(j - D) * D + k];
    __nv_bfloat16 hi = __float2bfloat16_rn(w);
    g_Whi[idx] = hi;
    g_Wlo[idx] = __float2bfloat16_rn(w - __bfloat162float(hi));
}

// ---------------- 3. count edges per destination --------------------------------
__global__ void count_kernel(const int* __restrict__ ei, int E) {
    int e = blockIdx.x * blockDim.x + threadIdx.x;
    if (e < E) atomicAdd(&g_deg[ei[e]], 1);
}

// ---------------- 4a/b/c. parallel exclusive scan -------------------------------
__global__ void scan1_kernel(int N) {
    __shared__ int sh[256];
    int t = threadIdx.x;
    int i = blockIdx.x * 256 + t;
    sh[t] = (i < N) ? g_deg[i] : 0;
    __syncthreads();
#pragma unroll
    for (int o = 128; o > 0; o >>= 1) {
        if (t < o) sh[t] += sh[t + o];
        __syncthreads();
    }
    if (t == 0) g_bsum[blockIdx.x] = sh[0];
}
__global__ void scan2_kernel(int NB, int N) {
    __shared__ int sh[160];
    int t = threadIdx.x;
    int v = (t < NB) ? g_bsum[t] : 0;
    sh[t] = v;
    __syncthreads();
    for (int o = 1; o < 160; o <<= 1) {
        int u = (t >= o) ? sh[t - o] : 0;
        __syncthreads();
        sh[t] += u;
        __syncthreads();
    }
    if (t < NB) g_bpre[t] = sh[t] - v;
    if (t == NB - 1) g_off[N] = sh[t];
}
__global__ void scan3_kernel(int N) {
    __shared__ int sh[256];
    int t = threadIdx.x;
    int i = blockIdx.x * 256 + t;
    int v = (i < N) ? g_deg[i] : 0;
    sh[t] = v;
    __syncthreads();
#pragma unroll
    for (int o = 1; o < 256; o <<= 1) {
        int u = (t >= o) ? sh[t - o] : 0;
        __syncthreads();
        sh[t] += u;
        __syncthreads();
    }
    if (i < N) {
        int e = sh[t] - v + g_bpre[blockIdx.x];
        g_off[i] = e;
        g_cur[i] = e;
    }
}

// ---------------- 5. bucket edge sources by destination -------------------------
__global__ void fill_kernel(const int* __restrict__ ei, int E) {
    int e = blockIdx.x * blockDim.x + threadIdx.x;
    if (e < E) {
        int r = ei[e];
        int c = ei[E + e];
        int p = atomicAdd(&g_cur[r], 1);
        g_bucket[p] = c;
    }
}

// ---------------- 6. WMMA bf16 3-term GEMM, cp.async double-buffered ------------
// C[m][j] = sum_k X[m][k]*Wcat[j][k]. CTA tile 128x128, 8 warps (warp 64x32).
// K chunks of 32, 2-stage cp.async pipeline. smem row stride 40 bf16 (80B).
#define GLDM 40
#define STAGE_ARR (128 * GLDM * 2)        // bytes per array (10240)
#define STAGE_BYTES (4 * STAGE_ARR)       // AsHi|AsLo|BsHi|BsLo (40960)
#define GEMM_SMEM (2 * STAGE_BYTES)       // 81920

__device__ __forceinline__ void gemm_stage_load(char* smem, int s, int row0, int j0,
                                                int kc, int tid) {
    char* base = smem + s * STAGE_BYTES;
    uint32_t uAhi = smem_u32(base);
    uint32_t uAlo = uAhi + STAGE_ARR;
    uint32_t uBhi = uAhi + 2 * STAGE_ARR;
    uint32_t uBlo = uAhi + 3 * STAGE_ARR;
#pragma unroll
    for (int t = 0; t < 2; t++) {
        int o = tid + t * 256;            // 0..511
        int row = o >> 2;                 // 0..127
        int seg = o & 3;                  // 16B segment
        uint32_t doff = row * 80 + seg * 16;
        size_t aoff = (size_t)(row0 + row) * D + kc + seg * 8;  // 8 bf16 = 16B
        size_t boff = (size_t)(j0 + row) * D + kc + seg * 8;
        CP_ASYNC16(uAhi + doff, (const char*)(g_Xhi + aoff));
        CP_ASYNC16(uAlo + doff, (const char*)(g_Xlo + aoff));
        CP_ASYNC16(uBhi + doff, (const char*)(g_Whi + boff));
        CP_ASYNC16(uBlo + doff, (const char*)(g_Wlo + boff));
    }
}

__global__ __launch_bounds__(256) void gemm_wmma_kernel(int M) {
    extern __shared__ char smem[];
    int tid = threadIdx.x;
    int wid = tid >> 5;
    int warp_row = wid >> 2;      // 0..1
    int warp_col = wid & 3;       // 0..3
    int row0 = blockIdx.x * 128;
    int j0 = blockIdx.y * 128;

    wmma::fragment<wmma::accumulator, 16, 16, 16, float> acc[4][2];
#pragma unroll
    for (int i = 0; i < 4; i++)
#pragma unroll
        for (int j = 0; j < 2; j++) wmma::fill_fragment(acc[i][j], 0.f);

    gemm_stage_load(smem, 0, row0, j0, 0, tid);
    CP_COMMIT();

#pragma unroll
    for (int c = 0; c < 8; c++) {
        int s = c & 1;
        if (c + 1 < 8) {
            gemm_stage_load(smem, (c + 1) & 1, row0, j0, (c + 1) * 32, tid);
            CP_COMMIT();
            CP_WAIT(1);
        } else {
            CP_WAIT(0);
        }
        __syncthreads();

        const __nv_bfloat16* AsHi = (const __nv_bfloat16*)(smem + s * STAGE_BYTES);
        const __nv_bfloat16* AsLo = AsHi + 128 * GLDM;
        const __nv_bfloat16* BsHi = AsHi + 2 * 128 * GLDM;
        const __nv_bfloat16* BsLo = AsHi + 3 * 128 * GLDM;
#pragma unroll
        for (int ks = 0; ks < 2; ks++) {
            wmma::fragment<wmma::matrix_a, 16, 16, 16, __nv_bfloat16, wmma::row_major> aHi[4], aLo[4];
            wmma::fragment<wmma::matrix_b, 16, 16, 16, __nv_bfloat16, wmma::col_major> bHi[2], bLo[2];
#pragma unroll
            for (int i = 0; i < 4; i++) {
                const __nv_bfloat16* pa = AsHi + (warp_row * 64 + i * 16) * GLDM + ks * 16;
                wmma::load_matrix_sync(aHi[i], pa, GLDM);
                wmma::load_matrix_sync(aLo[i], pa + 128 * GLDM, GLDM);
            }
#pragma unroll
            for (int j = 0; j < 2; j++) {
                const __nv_bfloat16* pb = BsHi + (warp_col * 32 + j * 16) * GLDM + ks * 16;
                wmma::load_matrix_sync(bHi[j], pb, GLDM);
                wmma::load_matrix_sync(bLo[j], pb + 128 * GLDM, GLDM);
            }
#pragma unroll
            for (int i = 0; i < 4; i++)
#pragma unroll
                for (int j = 0; j < 2; j++) {
                    wmma::mma_sync(acc[i][j], aHi[i], bHi[j], acc[i][j]);
                    wmma::mma_sync(acc[i][j], aHi[i], bLo[j], acc[i][j]);
                    wmma::mma_sync(acc[i][j], aLo[i], bHi[j], acc[i][j]);
                }
        }
        __syncthreads();
    }

    // epilogue (g_C has 128 pad rows beyond XPAD; X pad rows are zero)
#pragma unroll
    for (int i = 0; i < 4; i++) {
        int r = row0 + warp_row * 64 + i * 16;
#pragma unroll
        for (int j = 0; j < 2; j++) {
            float* cp = g_C + (size_t)r * NC + j0 + warp_col * 32 + j * 16;
            wmma::store_matrix_sync(cp, acc[i][j], NC, wmma::mem_row_major);
        }
    }
}

// ---------------- 7. row-normalize each 256-wide half of C ----------------------
__global__ void norm_kernel(int N2) {
    int w = (blockIdx.x * blockDim.x + threadIdx.x) >> 5;
    int lane = threadIdx.x & 31;
    if (w >= N2) return;
    float* p = g_C + (size_t)w * D;
    float v[8];
    float ss = 0.f;
#pragma unroll
    for (int k = 0; k < 8; k++) {
        float t = p[k * 32 + lane];
        v[k] = t;
        ss += t * t;
    }
    ss = warp_sum(ss);
    if (ss == 0.f) {
#pragma unroll
        for (int k = 0; k < 8; k++) p[k * 32 + lane] = 0.0625f;
    } else {
        float inv = 1.f / fmaxf(sqrtf(ss), 1e-8f);
#pragma unroll
        for (int k = 0; k < 8; k++) p[k * 32 + lane] = v[k] * inv;
    }
}

// ---------------- 8. aggregation + blend + final normalize (1 warp / node) ------
__global__ void agg_kernel(float* __restrict__ out, int N) {
    int w = (blockIdx.x * blockDim.x + threadIdx.x) >> 5;
    int lane = threadIdx.x & 31;
    if (w >= N) return;
    int beg = g_off[w], end = g_off[w + 1];
    float acc[8] = {0.f, 0.f, 0.f, 0.f, 0.f, 0.f, 0.f, 0.f};
    float acch = 0.f;
    for (int e = beg; e < end; e++) {
        int c = g_bucket[e];
        const float* p = g_C + (size_t)c * NC + D;
#pragma unroll
        for (int k = 0; k < 8; k++) acc[k] += p[k * 32 + lane];
        acch += g_habs[c];
    }
    float ss = 0.f;
#pragma unroll
    for (int k = 0; k < 8; k++) ss += acc[k] * acc[k];
    ss = warp_sum(ss);
    float p2[8];
    if (ss == 0.f) {
#pragma unroll
        for (int k = 0; k < 8; k++) p2[k] = 0.0625f;
    } else {
        float iv = 1.f / fmaxf(sqrtf(ss), 1e-8f);
#pragma unroll
        for (int k = 0; k < 8; k++) p2[k] = acc[k] * iv;
    }
    float p2h = 1.f + acch;
    const float t = 0.5f / (1.0f - 0.5f + 1e-8f);  // == 1.0f in fp32, as reference
    const float* srow = g_C + (size_t)w * NC;
    float avv[8];
    float ss2 = 0.f;
#pragma unroll
    for (int k = 0; k < 8; k++) {
        float a = srow[k * 32 + lane] * t + p2[k];
        avv[k] = a;
        ss2 += a * a;
    }
    ss2 = warp_sum(ss2);
    float* orow = out + (size_t)w * (D + 1);
    if (ss2 == 0.f) {
#pragma unroll
        for (int k = 0; k < 8; k++) orow[k * 32 + lane] = 0.0625f;
    } else {
        float iv = 1.f / fmaxf(sqrtf(ss2), 1e-8f);
#pragma unroll
        for (int k = 0; k < 8; k++) orow[k * 32 + lane] = avv[k] * iv;
    }
    if (lane == 0) {
        float p1h = g_habs[w];
        orow[D] = (p1h * t + p2h) / (t + 1.0f);
    }
}

// ---------------- launch --------------------------------------------------------
extern "C" void kernel_launch(void* const* d_in, const int* in_sizes, int n_in,
                              void* d_out, int out_size) {
    const float* x  = (const float*)d_in[0];
    const float* Ws = (const float*)d_in[1];
    const float* Wn = (const float*)d_in[2];
    const int*   ei = (const int*)d_in[3];
    int N = in_sizes[0] / (D + 1);
    if (N > NMAX) N = NMAX;
    int E = in_sizes[3] / 2;
    if (E > EMAX) E = EMAX;
    float* out = (float*)d_out;

    cudaFuncSetAttribute(gemm_wmma_kernel, cudaFuncAttributeMaxDynamicSharedMemorySize,
                         GEMM_SMEM);

    int warpBlocks = (N * 32 + 255) / 256;
    int NB = (N + 255) / 256;
    prep_kernel<<<warpBlocks, 256>>>(x, N);
    wsplit_kernel<<<(NC * D + 255) / 256, 256>>>(Ws, Wn);
    count_kernel<<<(E + 255) / 256, 256>>>(ei, E);
    scan1_kernel<<<NB, 256>>>(N);
    scan2_kernel<<<1, 160>>>(NB, N);
    scan3_kernel<<<NB, 256>>>(N);
    fill_kernel<<<(E + 255) / 256, 256>>>(ei, E);
    dim3 gg((N + 127) / 128, NC / 128);
    gemm_wmma_kernel<<<gg, 256, GEMM_SMEM>>>(N);
    norm_kernel<<<(2 * N * 32 + 255) / 256, 256>>>(2 * N);
    agg_kernel<<<warpBlocks, 256>>>(out, N);
}

// round 12
// speedup vs baseline: 1.8789x; 1.0988x over previous
#include <cuda_runtime.h>
#include <cuda_bf16.h>
#include <cuda_fp16.h>
#include <mma.h>
#include <cstdint>

using namespace nvcuda;

#define NMAX 20000
#define XPAD 20096           // NMAX rounded up to 128-row tiles
#define EMAX 320000
#define D 256
#define NC 512   // self 256 cols | neigh 256 cols

// ---------------- scratch (__device__ globals) ----------------------------------
__device__ __align__(16) __nv_bfloat16 g_Xhi[(size_t)XPAD * D];
__device__ __align__(16) __nv_bfloat16 g_Xlo[(size_t)XPAD * D];
__device__ __align__(16) __nv_bfloat16 g_Whi[NC * D];   // [n][k], K-major
__device__ __align__(16) __nv_bfloat16 g_Wlo[NC * D];
__device__ __align__(16) float g_C[(size_t)(XPAD + 128) * NC];  // raw GEMM out
__device__ __align__(16) __half g_Nh[(size_t)NMAX * D];         // normalized neigh half, fp16
__device__ __align__(16) float2 g_sinv[NMAX];                   // (inv, off) for self half
__device__ float g_habs[NMAX];
__device__ int g_deg[NMAX];
__device__ int g_off[NMAX + 1];
__device__ int g_cur[NMAX];
__device__ int g_bucket[EMAX];
__device__ int g_bsum[160];
__device__ int g_bpre[160];

__device__ __forceinline__ float warp_sum(float v) {
#pragma unroll
    for (int o = 16; o > 0; o >>= 1) v += __shfl_xor_sync(0xffffffffu, v, o);
    return v;
}
__device__ __forceinline__ uint32_t smem_u32(const void* p) {
    uint32_t a;
    asm("{ .reg .u64 t; cvta.to.shared.u64 t, %1; cvt.u32.u64 %0, t; }" : "=r"(a) : "l"(p));
    return a;
}
#define CP_ASYNC16(dst, src) \
    asm volatile("cp.async.cg.shared.global [%0], [%1], 16;" :: "r"(dst), "l"(src))
#define CP_COMMIT() asm volatile("cp.async.commit_group;" ::: "memory")
#define CP_WAIT(n)  asm volatile("cp.async.wait_group %0;" :: "n"(n) : "memory")

// ---------------- 1. fused: per-node normalize+split  |  W concat+split ---------
__global__ void prep_wsplit_kernel(const float* __restrict__ x,
                                   const float* __restrict__ Ws,
                                   const float* __restrict__ Wn,
                                   int N, int PB) {
    if (blockIdx.x < PB) {
        // ---- prep part ----
        int gid = blockIdx.x * blockDim.x + threadIdx.x;
        if (gid < N) g_deg[gid] = 0;
        int w = gid >> 5;
        int lane = threadIdx.x & 31;
        if (w >= N) return;
        const float* xr = x + (size_t)w * (D + 1);
        float v[8];
        float ss = 0.f;
        bool nz = false;
#pragma unroll
        for (int k = 0; k < 8; k++) {
            float t = xr[k * 32 + lane];
            v[k] = t; ss += t * t; nz |= (t != 0.f);
        }
        unsigned m = __ballot_sync(0xffffffffu, nz);
        ss = warp_sum(ss);
        float h = xr[D];
        float s0 = (h < 0.f) ? -1.f : 1.f;
        float scale;
        if (m == 0u) {
#pragma unroll
            for (int k = 0; k < 8; k++) v[k] = 1.f;
            scale = s0 * (1.f / 16.f);
        } else {
            scale = s0 / fmaxf(sqrtf(ss), 1e-8f);
        }
#pragma unroll
        for (int k = 0; k < 8; k++) {
            float val = v[k] * scale;
            __nv_bfloat16 hi = __float2bfloat16_rn(val);
            float lo = val - __bfloat162float(hi);
            size_t idx = (size_t)w * D + k * 32 + lane;
            g_Xhi[idx] = hi;
            g_Xlo[idx] = __float2bfloat16_rn(lo);
        }
        if (lane == 0) g_habs[w] = h * s0;
    } else {
        // ---- wsplit part ----
        int idx = (blockIdx.x - PB) * blockDim.x + threadIdx.x;
        if (idx >= NC * D) return;
        int j = idx / D, k = idx % D;
        float w = (j < D) ? Ws[j * D + k] : Wn[(j - D) * D + k];
        __nv_bfloat16 hi = __float2bfloat16_rn(w);
        g_Whi[idx] = hi;
        g_Wlo[idx] = __float2bfloat16_rn(w - __bfloat162float(hi));
    }
}

// ---------------- 2. count edges per destination --------------------------------
__global__ void count_kernel(const int* __restrict__ ei, int E) {
    int e = blockIdx.x * blockDim.x + threadIdx.x;
    if (e < E) atomicAdd(&g_deg[ei[e]], 1);
}

// ---------------- 3a/b/c. parallel exclusive scan -------------------------------
__global__ void scan1_kernel(int N) {
    __shared__ int sh[256];
    int t = threadIdx.x;
    int i = blockIdx.x * 256 + t;
    sh[t] = (i < N) ? g_deg[i] : 0;
    __syncthreads();
#pragma unroll
    for (int o = 128; o > 0; o >>= 1) {
        if (t < o) sh[t] += sh[t + o];
        __syncthreads();
    }
    if (t == 0) g_bsum[blockIdx.x] = sh[0];
}
__global__ void scan2_kernel(int NB, int N) {
    __shared__ int sh[160];
    int t = threadIdx.x;
    int v = (t < NB) ? g_bsum[t] : 0;
    sh[t] = v;
    __syncthreads();
    for (int o = 1; o < 160; o <<= 1) {
        int u = (t >= o) ? sh[t - o] : 0;
        __syncthreads();
        sh[t] += u;
        __syncthreads();
    }
    if (t < NB) g_bpre[t] = sh[t] - v;
    if (t == NB - 1) g_off[N] = sh[t];
}
__global__ void scan3_kernel(int N) {
    __shared__ int sh[256];
    int t = threadIdx.x;
    int i = blockIdx.x * 256 + t;
    int v = (i < N) ? g_deg[i] : 0;
    sh[t] = v;
    __syncthreads();
#pragma unroll
    for (int o = 1; o < 256; o <<= 1) {
        int u = (t >= o) ? sh[t - o] : 0;
        __syncthreads();
        sh[t] += u;
        __syncthreads();
    }
    if (i < N) {
        int e = sh[t] - v + g_bpre[blockIdx.x];
        g_off[i] = e;
        g_cur[i] = e;
    }
}

// ---------------- 4. bucket edge sources by destination -------------------------
__global__ void fill_kernel(const int* __restrict__ ei, int E) {
    int e = blockIdx.x * blockDim.x + threadIdx.x;
    if (e < E) {
        int r = ei[e];
        int c = ei[E + e];
        int p = atomicAdd(&g_cur[r], 1);
        g_bucket[p] = c;
    }
}

// ---------------- 5. WMMA bf16 3-term GEMM, cp.async double-buffered ------------
#define GLDM 40
#define STAGE_ARR (128 * GLDM * 2)        // bytes per array (10240)
#define STAGE_BYTES (4 * STAGE_ARR)       // AsHi|AsLo|BsHi|BsLo (40960)
#define GEMM_SMEM (2 * STAGE_BYTES)       // 81920

__device__ __forceinline__ void gemm_stage_load(char* smem, int s, int row0, int j0,
                                                int kc, int tid) {
    char* base = smem + s * STAGE_BYTES;
    uint32_t uAhi = smem_u32(base);
    uint32_t uAlo = uAhi + STAGE_ARR;
    uint32_t uBhi = uAhi + 2 * STAGE_ARR;
    uint32_t uBlo = uAhi + 3 * STAGE_ARR;
#pragma unroll
    for (int t = 0; t < 2; t++) {
        int o = tid + t * 256;            // 0..511
        int row = o >> 2;                 // 0..127
        int seg = o & 3;                  // 16B segment
        uint32_t doff = row * 80 + seg * 16;
        size_t aoff = (size_t)(row0 + row) * D + kc + seg * 8;  // 8 bf16 = 16B
        size_t boff = (size_t)(j0 + row) * D + kc + seg * 8;
        CP_ASYNC16(uAhi + doff, (const char*)(g_Xhi + aoff));
        CP_ASYNC16(uAlo + doff, (const char*)(g_Xlo + aoff));
        CP_ASYNC16(uBhi + doff, (const char*)(g_Whi + boff));
        CP_ASYNC16(uBlo + doff, (const char*)(g_Wlo + boff));
    }
}

__global__ __launch_bounds__(256) void gemm_wmma_kernel(int M) {
    extern __shared__ char smem[];
    int tid = threadIdx.x;
    int wid = tid >> 5;
    int warp_row = wid >> 2;      // 0..1
    int warp_col = wid & 3;       // 0..3
    int row0 = blockIdx.x * 128;
    int j0 = blockIdx.y * 128;

    wmma::fragment<wmma::accumulator, 16, 16, 16, float> acc[4][2];
#pragma unroll
    for (int i = 0; i < 4; i++)
#pragma unroll
        for (int j = 0; j < 2; j++) wmma::fill_fragment(acc[i][j], 0.f);

    gemm_stage_load(smem, 0, row0, j0, 0, tid);
    CP_COMMIT();

#pragma unroll
    for (int c = 0; c < 8; c++) {
        int s = c & 1;
        if (c + 1 < 8) {
            gemm_stage_load(smem, (c + 1) & 1, row0, j0, (c + 1) * 32, tid);
            CP_COMMIT();
            CP_WAIT(1);
        } else {
            CP_WAIT(0);
        }
        __syncthreads();

        const __nv_bfloat16* AsHi = (const __nv_bfloat16*)(smem + s * STAGE_BYTES);
        const __nv_bfloat16* BsHi = AsHi + 2 * 128 * GLDM;
#pragma unroll
        for (int ks = 0; ks < 2; ks++) {
            wmma::fragment<wmma::matrix_a, 16, 16, 16, __nv_bfloat16, wmma::row_major> aHi[4], aLo[4];
            wmma::fragment<wmma::matrix_b, 16, 16, 16, __nv_bfloat16, wmma::col_major> bHi[2], bLo[2];
#pragma unroll
            for (int i = 0; i < 4; i++) {
                const __nv_bfloat16* pa = AsHi + (warp_row * 64 + i * 16) * GLDM + ks * 16;
                wmma::load_matrix_sync(aHi[i], pa, GLDM);
                wmma::load_matrix_sync(aLo[i], pa + 128 * GLDM, GLDM);
            }
#pragma unroll
            for (int j = 0; j < 2; j++) {
                const __nv_bfloat16* pb = BsHi + (warp_col * 32 + j * 16) * GLDM + ks * 16;
                wmma::load_matrix_sync(bHi[j], pb, GLDM);
                wmma::load_matrix_sync(bLo[j], pb + 128 * GLDM, GLDM);
            }
#pragma unroll
            for (int i = 0; i < 4; i++)
#pragma unroll
                for (int j = 0; j < 2; j++) {
                    wmma::mma_sync(acc[i][j], aHi[i], bHi[j], acc[i][j]);
                    wmma::mma_sync(acc[i][j], aHi[i], bLo[j], acc[i][j]);
                    wmma::mma_sync(acc[i][j], aLo[i], bHi[j], acc[i][j]);
                }
        }
        __syncthreads();
    }

#pragma unroll
    for (int i = 0; i < 4; i++) {
        int r = row0 + warp_row * 64 + i * 16;
#pragma unroll
        for (int j = 0; j < 2; j++) {
            float* cp = g_C + (size_t)r * NC + j0 + warp_col * 32 + j * 16;
            wmma::store_matrix_sync(cp, acc[i][j], NC, wmma::mem_row_major);
        }
    }
}

// ---------------- 6. per-half-row: self -> (inv,off); neigh -> fp16 row ---------
__global__ void norm_kernel(int N2) {
    int w = (blockIdx.x * blockDim.x + threadIdx.x) >> 5;
    int lane = threadIdx.x & 31;
    if (w >= N2) return;
    const float* p = g_C + (size_t)w * D;   // half-row w (NC = 2*D)
    float v[8];
    float ss = 0.f;
#pragma unroll
    for (int k = 0; k < 8; k++) {
        float t = p[k * 32 + lane];
        v[k] = t;
        ss += t * t;
    }
    ss = warp_sum(ss);
    int node = w >> 1;
    if ((w & 1) == 0) {
        // self half: record inverse-norm (+offset for the all-zero case)
        if (lane == 0)
            g_sinv[node] = (ss == 0.f) ? make_float2(0.f, 0.0625f)
                                       : make_float2(1.f / fmaxf(sqrtf(ss), 1e-8f), 0.f);
    } else {
        // neighbor half: write normalized row as fp16
        __half* q = g_Nh + (size_t)node * D;
        if (ss == 0.f) {
            __half c = __float2half(0.0625f);
#pragma unroll
            for (int k = 0; k < 8; k++) q[k * 32 + lane] = c;
        } else {
            float inv = 1.f / fmaxf(sqrtf(ss), 1e-8f);
#pragma unroll
            for (int k = 0; k < 8; k++) q[k * 32 + lane] = __float2half(v[k] * inv);
        }
    }
}

// ---------------- 7. aggregation + blend + final normalize (1 warp / node) ------
// Lane owns element pairs (2*(k*32+lane), +1) for k=0..3.
__global__ void agg_kernel(float* __restrict__ out, int N) {
    int w = (blockIdx.x * blockDim.x + threadIdx.x) >> 5;
    int lane = threadIdx.x & 31;
    if (w >= N) return;
    int beg = g_off[w], end = g_off[w + 1];
    float accx[4] = {0.f, 0.f, 0.f, 0.f};
    float accy[4] = {0.f, 0.f, 0.f, 0.f};
    float acch = 0.f;
    const __half2* nh = (const __half2*)g_Nh;
    for (int e = beg; e < end; e++) {
        int c = g_bucket[e];
        const __half2* p = nh + (size_t)c * (D / 2);
#pragma unroll
        for (int k = 0; k < 4; k++) {
            float2 f = __half22float2(p[k * 32 + lane]);
            accx[k] += f.x;
            accy[k] += f.y;
        }
        acch += g_habs[c];
    }
    float ss = 0.f;
#pragma unroll
    for (int k = 0; k < 4; k++) ss += accx[k] * accx[k] + accy[k] * accy[k];
    ss = warp_sum(ss);
    float p2x[4], p2y[4];
    if (ss == 0.f) {
#pragma unroll
        for (int k = 0; k < 4; k++) { p2x[k] = 0.0625f; p2y[k] = 0.0625f; }
    } else {
        float iv = 1.f / fmaxf(sqrtf(ss), 1e-8f);
#pragma unroll
        for (int k = 0; k < 4; k++) { p2x[k] = accx[k] * iv; p2y[k] = accy[k] * iv; }
    }
    float p2h = 1.f + acch;
    const float t = 0.5f / (1.0f - 0.5f + 1e-8f);  // == 1.0f in fp32, as reference
    float2 si = g_sinv[w];                          // (inv, off)
    const float2* srow2 = (const float2*)(g_C + (size_t)w * NC);
    float avx[4], avy[4];
    float ss2 = 0.f;
#pragma unroll
    for (int k = 0; k < 4; k++) {
        float2 s = srow2[k * 32 + lane];
        float ax = (s.x * si.x + si.y) * t + p2x[k];
        float ay = (s.y * si.x + si.y) * t + p2y[k];
        avx[k] = ax; avy[k] = ay;
        ss2 += ax * ax + ay * ay;
    }
    ss2 = warp_sum(ss2);
    float* orow = out + (size_t)w * (D + 1);
    if (ss2 == 0.f) {
#pragma unroll
        for (int k = 0; k < 4; k++) {
            int j = 2 * (k * 32 + lane);
            orow[j] = 0.0625f;
            orow[j + 1] = 0.0625f;
        }
    } else {
        float iv = 1.f / fmaxf(sqrtf(ss2), 1e-8f);
#pragma unroll
        for (int k = 0; k < 4; k++) {
            int j = 2 * (k * 32 + lane);
            orow[j] = avx[k] * iv;
            orow[j + 1] = avy[k] * iv;
        }
    }
    if (lane == 0) {
        float p1h = g_habs[w];
        orow[D] = (p1h * t + p2h) / (t + 1.0f);
    }
}

// ---------------- launch --------------------------------------------------------
extern "C" void kernel_launch(void* const* d_in, const int* in_sizes, int n_in,
                              void* d_out, int out_size) {
    const float* x  = (const float*)d_in[0];
    const float* Ws = (const float*)d_in[1];
    const float* Wn = (const float*)d_in[2];
    const int*   ei = (const int*)d_in[3];
    int N = in_sizes[0] / (D + 1);
    if (N > NMAX) N = NMAX;
    int E = in_sizes[3] / 2;
    if (E > EMAX) E = EMAX;
    float* out = (float*)d_out;

    cudaFuncSetAttribute(gemm_wmma_kernel, cudaFuncAttributeMaxDynamicSharedMemorySize,
                         GEMM_SMEM);

    int warpBlocks = (N * 32 + 255) / 256;
    int wsplitBlocks = (NC * D + 255) / 256;
    int NB = (N + 255) / 256;
    prep_wsplit_kernel<<<warpBlocks + wsplitBlocks, 256>>>(x, Ws, Wn, N, warpBlocks);
    count_kernel<<<(E + 255) / 256, 256>>>(ei, E);
    scan1_kernel<<<NB, 256>>>(N);
    scan2_kernel<<<1, 160>>>(NB, N);
    scan3_kernel<<<NB, 256>>>(N);
    fill_kernel<<<(E + 255) / 256, 256>>>(ei, E);
    dim3 gg((N + 127) / 128, NC / 128);
    gemm_wmma_kernel<<<gg, 256, GEMM_SMEM>>>(N);
    norm_kernel<<<(2 * N * 32 + 255) / 256, 256>>>(2 * N);
    agg_kernel<<<warpBlocks, 256>>>(out, N);
}

// round 14
// speedup vs baseline: 2.0595x; 1.0961x over previous
#include <cuda_runtime.h>
#include <cuda_bf16.h>
#include <cuda_fp16.h>
#include <mma.h>
#include <cstdint>

using namespace nvcuda;

#define NMAX 20000
#define XPAD 20096           // NMAX rounded up to 128-row tiles
#define EMAX 320000
#define D 256
#define NC 512   // self 256 cols | neigh 256 cols

// ---------------- scratch (__device__ globals) ----------------------------------
__device__ __align__(16) __nv_bfloat16 g_Xhi[(size_t)XPAD * D];
__device__ __align__(16) __nv_bfloat16 g_Xlo[(size_t)XPAD * D];
__device__ __align__(16) __nv_bfloat16 g_Whi[NC * D];   // [n][k], K-major
__device__ __align__(16) __nv_bfloat16 g_Wlo[NC * D];
__device__ __align__(16) float g_C[(size_t)(XPAD + 128) * NC];  // raw GEMM out
__device__ __align__(16) __half g_Nh[(size_t)NMAX * D];         // normalized neigh half, fp16
__device__ __align__(16) float2 g_sinv[NMAX];                   // (inv, off) for self half
__device__ float g_habs[NMAX];
__device__ int g_deg[NMAX];
__device__ int g_off[NMAX + 1];
__device__ int g_cur[NMAX];
__device__ int g_bucket[EMAX];
__device__ int g_bsum[160];
__device__ int g_bpre[160];

__device__ __forceinline__ float warp_sum(float v) {
#pragma unroll
    for (int o = 16; o > 0; o >>= 1) v += __shfl_xor_sync(0xffffffffu, v, o);
    return v;
}
__device__ __forceinline__ uint32_t smem_u32(const void* p) {
    uint32_t a;
    asm("{ .reg .u64 t; cvta.to.shared.u64 t, %1; cvt.u32.u64 %0, t; }" : "=r"(a) : "l"(p));
    return a;
}
#define CP_ASYNC16(dst, src) \
    asm volatile("cp.async.cg.shared.global [%0], [%1], 16;" :: "r"(dst), "l"(src))
#define CP_COMMIT() asm volatile("cp.async.commit_group;" ::: "memory")
#define CP_WAIT(n)  asm volatile("cp.async.wait_group %0;" :: "n"(n) : "memory")

// ---------------- 1. fused: per-node normalize+split  |  W concat+split ---------
__global__ void prep_wsplit_kernel(const float* __restrict__ x,
                                   const float* __restrict__ Ws,
                                   const float* __restrict__ Wn,
                                   int N, int PB) {
    if (blockIdx.x < PB) {
        // ---- prep part ----
        int gid = blockIdx.x * blockDim.x + threadIdx.x;
        int w = gid >> 5;
        int lane = threadIdx.x & 31;
        if (w >= N) return;
        const float* xr = x + (size_t)w * (D + 1);
        float v[8];
        float ss = 0.f;
        bool nz = false;
#pragma unroll
        for (int k = 0; k < 8; k++) {
            float t = xr[k * 32 + lane];
            v[k] = t; ss += t * t; nz |= (t != 0.f);
        }
        unsigned m = __ballot_sync(0xffffffffu, nz);
        ss = warp_sum(ss);
        float h = xr[D];
        float s0 = (h < 0.f) ? -1.f : 1.f;
        float scale;
        if (m == 0u) {
#pragma unroll
            for (int k = 0; k < 8; k++) v[k] = 1.f;
            scale = s0 * (1.f / 16.f);
        } else {
            scale = s0 / fmaxf(sqrtf(ss), 1e-8f);
        }
#pragma unroll
        for (int k = 0; k < 8; k++) {
            float val = v[k] * scale;
            __nv_bfloat16 hi = __float2bfloat16_rn(val);
            float lo = val - __bfloat162float(hi);
            size_t idx = (size_t)w * D + k * 32 + lane;
            g_Xhi[idx] = hi;
            g_Xlo[idx] = __float2bfloat16_rn(lo);
        }
        if (lane == 0) g_habs[w] = h * s0;
    } else {
        // ---- wsplit part ----
        int idx = (blockIdx.x - PB) * blockDim.x + threadIdx.x;
        if (idx >= NC * D) return;
        int j = idx / D, k = idx % D;
        float w = (j < D) ? Ws[j * D + k] : Wn[(j - D) * D + k];
        __nv_bfloat16 hi = __float2bfloat16_rn(w);
        g_Whi[idx] = hi;
        g_Wlo[idx] = __float2bfloat16_rn(w - __bfloat162float(hi));
    }
}

// ---------------- 2a. zero degree counters (edge stream head) -------------------
__global__ void zerodeg_kernel(int N) {
    int i = blockIdx.x * blockDim.x + threadIdx.x;
    if (i < N) g_deg[i] = 0;
}

// ---------------- 2b. count edges per destination -------------------------------
__global__ void count_kernel(const int* __restrict__ ei, int E) {
    int e = blockIdx.x * blockDim.x + threadIdx.x;
    if (e < E) atomicAdd(&g_deg[ei[e]], 1);
}

// ---------------- 3a/b/c. parallel exclusive scan -------------------------------
__global__ void scan1_kernel(int N) {
    __shared__ int sh[256];
    int t = threadIdx.x;
    int i = blockIdx.x * 256 + t;
    sh[t] = (i < N) ? g_deg[i] : 0;
    __syncthreads();
#pragma unroll
    for (int o = 128; o > 0; o >>= 1) {
        if (t < o) sh[t] += sh[t + o];
        __syncthreads();
    }
    if (t == 0) g_bsum[blockIdx.x] = sh[0];
}
__global__ void scan2_kernel(int NB, int N) {
    __shared__ int sh[160];
    int t = threadIdx.x;
    int v = (t < NB) ? g_bsum[t] : 0;
    sh[t] = v;
    __syncthreads();
    for (int o = 1; o < 160; o <<= 1) {
        int u = (t >= o) ? sh[t - o] : 0;
        __syncthreads();
        sh[t] += u;
        __syncthreads();
    }
    if (t < NB) g_bpre[t] = sh[t] - v;
    if (t == NB - 1) g_off[N] = sh[t];
}
__global__ void scan3_kernel(int N) {
    __shared__ int sh[256];
    int t = threadIdx.x;
    int i = blockIdx.x * 256 + t;
    int v = (i < N) ? g_deg[i] : 0;
    sh[t] = v;
    __syncthreads();
#pragma unroll
    for (int o = 1; o < 256; o <<= 1) {
        int u = (t >= o) ? sh[t - o] : 0;
        __syncthreads();
        sh[t] += u;
        __syncthreads();
    }
    if (i < N) {
        int e = sh[t] - v + g_bpre[blockIdx.x];
        g_off[i] = e;
        g_cur[i] = e;
    }
}

// ---------------- 4. bucket edge sources by destination -------------------------
__global__ void fill_kernel(const int* __restrict__ ei, int E) {
    int e = blockIdx.x * blockDim.x + threadIdx.x;
    if (e < E) {
        int r = ei[e];
        int c = ei[E + e];
        int p = atomicAdd(&g_cur[r], 1);
        g_bucket[p] = c;
    }
}

// ---------------- 5. WMMA bf16 3-term GEMM, cp.async double-buffered ------------
#define GLDM 40
#define STAGE_ARR (128 * GLDM * 2)        // bytes per array (10240)
#define STAGE_BYTES (4 * STAGE_ARR)       // AsHi|AsLo|BsHi|BsLo (40960)
#define GEMM_SMEM (2 * STAGE_BYTES)       // 81920

__device__ __forceinline__ void gemm_stage_load(char* smem, int s, int row0, int j0,
                                                int kc, int tid) {
    char* base = smem + s * STAGE_BYTES;
    uint32_t uAhi = smem_u32(base);
    uint32_t uAlo = uAhi + STAGE_ARR;
    uint32_t uBhi = uAhi + 2 * STAGE_ARR;
    uint32_t uBlo = uAhi + 3 * STAGE_ARR;
#pragma unroll
    for (int t = 0; t < 2; t++) {
        int o = tid + t * 256;            // 0..511
        int row = o >> 2;                 // 0..127
        int seg = o & 3;                  // 16B segment
        uint32_t doff = row * 80 + seg * 16;
        size_t aoff = (size_t)(row0 + row) * D + kc + seg * 8;  // 8 bf16 = 16B
        size_t boff = (size_t)(j0 + row) * D + kc + seg * 8;
        CP_ASYNC16(uAhi + doff, (const char*)(g_Xhi + aoff));
        CP_ASYNC16(uAlo + doff, (const char*)(g_Xlo + aoff));
        CP_ASYNC16(uBhi + doff, (const char*)(g_Whi + boff));
        CP_ASYNC16(uBlo + doff, (const char*)(g_Wlo + boff));
    }
}

__global__ __launch_bounds__(256) void gemm_wmma_kernel(int M) {
    extern __shared__ char smem[];
    int tid = threadIdx.x;
    int wid = tid >> 5;
    int warp_row = wid >> 2;      // 0..1
    int warp_col = wid & 3;       // 0..3
    int row0 = blockIdx.x * 128;
    int j0 = blockIdx.y * 128;

    wmma::fragment<wmma::accumulator, 16, 16, 16, float> acc[4][2];
#pragma unroll
    for (int i = 0; i < 4; i++)
#pragma unroll
        for (int j = 0; j < 2; j++) wmma::fill_fragment(acc[i][j], 0.f);

    gemm_stage_load(smem, 0, row0, j0, 0, tid);
    CP_COMMIT();

#pragma unroll
    for (int c = 0; c < 8; c++) {
        int s = c & 1;
        if (c + 1 < 8) {
            gemm_stage_load(smem, (c + 1) & 1, row0, j0, (c + 1) * 32, tid);
            CP_COMMIT();
            CP_WAIT(1);
        } else {
            CP_WAIT(0);
        }
        __syncthreads();

        const __nv_bfloat16* AsHi = (const __nv_bfloat16*)(smem + s * STAGE_BYTES);
        const __nv_bfloat16* BsHi = AsHi + 2 * 128 * GLDM;
#pragma unroll
        for (int ks = 0; ks < 2; ks++) {
            wmma::fragment<wmma::matrix_a, 16, 16, 16, __nv_bfloat16, wmma::row_major> aHi[4], aLo[4];
            wmma::fragment<wmma::matrix_b, 16, 16, 16, __nv_bfloat16, wmma::col_major> bHi[2], bLo[2];
#pragma unroll
            for (int i = 0; i < 4; i++) {
                const __nv_bfloat16* pa = AsHi + (warp_row * 64 + i * 16) * GLDM + ks * 16;
                wmma::load_matrix_sync(aHi[i], pa, GLDM);
                wmma::load_matrix_sync(aLo[i], pa + 128 * GLDM, GLDM);
            }
#pragma unroll
            for (int j = 0; j < 2; j++) {
                const __nv_bfloat16* pb = BsHi + (warp_col * 32 + j * 16) * GLDM + ks * 16;
                wmma::load_matrix_sync(bHi[j], pb, GLDM);
                wmma::load_matrix_sync(bLo[j], pb + 128 * GLDM, GLDM);
            }
#pragma unroll
            for (int i = 0; i < 4; i++)
#pragma unroll
                for (int j = 0; j < 2; j++) {
                    wmma::mma_sync(acc[i][j], aHi[i], bHi[j], acc[i][j]);
                    wmma::mma_sync(acc[i][j], aHi[i], bLo[j], acc[i][j]);
                    wmma::mma_sync(acc[i][j], aLo[i], bHi[j], acc[i][j]);
                }
        }
        __syncthreads();
    }

#pragma unroll
    for (int i = 0; i < 4; i++) {
        int r = row0 + warp_row * 64 + i * 16;
#pragma unroll
        for (int j = 0; j < 2; j++) {
            float* cp = g_C + (size_t)r * NC + j0 + warp_col * 32 + j * 16;
            wmma::store_matrix_sync(cp, acc[i][j], NC, wmma::mem_row_major);
        }
    }
}

// ---------------- 6. per-half-row: self -> (inv,off); neigh -> fp16 row ---------
__global__ void norm_kernel(int N2) {
    int w = (blockIdx.x * blockDim.x + threadIdx.x) >> 5;
    int lane = threadIdx.x & 31;
    if (w >= N2) return;
    const float* p = g_C + (size_t)w * D;   // half-row w (NC = 2*D)
    float v[8];
    float ss = 0.f;
#pragma unroll
    for (int k = 0; k < 8; k++) {
        float t = p[k * 32 + lane];
        v[k] = t;
        ss += t * t;
    }
    ss = warp_sum(ss);
    int node = w >> 1;
    if ((w & 1) == 0) {
        if (lane == 0)
            g_sinv[node] = (ss == 0.f) ? make_float2(0.f, 0.0625f)
                                       : make_float2(1.f / fmaxf(sqrtf(ss), 1e-8f), 0.f);
    } else {
        __half* q = g_Nh + (size_t)node * D;
        if (ss == 0.f) {
            __half c = __float2half(0.0625f);
#pragma unroll
            for (int k = 0; k < 8; k++) q[k * 32 + lane] = c;
        } else {
            float inv = 1.f / fmaxf(sqrtf(ss), 1e-8f);
#pragma unroll
            for (int k = 0; k < 8; k++) q[k * 32 + lane] = __float2half(v[k] * inv);
        }
    }
}

// ---------------- 7. aggregation + blend + final normalize (1 warp / node) ------
__global__ void agg_kernel(float* __restrict__ out, int N) {
    int w = (blockIdx.x * blockDim.x + threadIdx.x) >> 5;
    int lane = threadIdx.x & 31;
    if (w >= N) return;
    int beg = g_off[w], end = g_off[w + 1];
    float accx[4] = {0.f, 0.f, 0.f, 0.f};
    float accy[4] = {0.f, 0.f, 0.f, 0.f};
    float acch = 0.f;
    const __half2* nh = (const __half2*)g_Nh;
    for (int e = beg; e < end; e++) {
        int c = g_bucket[e];
        const __half2* p = nh + (size_t)c * (D / 2);
#pragma unroll
        for (int k = 0; k < 4; k++) {
            float2 f = __half22float2(p[k * 32 + lane]);
            accx[k] += f.x;
            accy[k] += f.y;
        }
        acch += g_habs[c];
    }
    float ss = 0.f;
#pragma unroll
    for (int k = 0; k < 4; k++) ss += accx[k] * accx[k] + accy[k] * accy[k];
    ss = warp_sum(ss);
    float p2x[4], p2y[4];
    if (ss == 0.f) {
#pragma unroll
        for (int k = 0; k < 4; k++) { p2x[k] = 0.0625f; p2y[k] = 0.0625f; }
    } else {
        float iv = 1.f / fmaxf(sqrtf(ss), 1e-8f);
#pragma unroll
        for (int k = 0; k < 4; k++) { p2x[k] = accx[k] * iv; p2y[k] = accy[k] * iv; }
    }
    float p2h = 1.f + acch;
    const float t = 0.5f / (1.0f - 0.5f + 1e-8f);  // == 1.0f in fp32, as reference
    float2 si = g_sinv[w];                          // (inv, off)
    const float2* srow2 = (const float2*)(g_C + (size_t)w * NC);
    float avx[4], avy[4];
    float ss2 = 0.f;
#pragma unroll
    for (int k = 0; k < 4; k++) {
        float2 s = srow2[k * 32 + lane];
        float ax = (s.x * si.x + si.y) * t + p2x[k];
        float ay = (s.y * si.x + si.y) * t + p2y[k];
        avx[k] = ax; avy[k] = ay;
        ss2 += ax * ax + ay * ay;
    }
    ss2 = warp_sum(ss2);
    float* orow = out + (size_t)w * (D + 1);
    if (ss2 == 0.f) {
#pragma unroll
        for (int k = 0; k < 4; k++) {
            int j = 2 * (k * 32 + lane);
            orow[j] = 0.0625f;
            orow[j + 1] = 0.0625f;
        }
    } else {
        float iv = 1.f / fmaxf(sqrtf(ss2), 1e-8f);
#pragma unroll
        for (int k = 0; k < 4; k++) {
            int j = 2 * (k * 32 + lane);
            orow[j] = avx[k] * iv;
            orow[j + 1] = avy[k] * iv;
        }
    }
    if (lane == 0) {
        float p1h = g_habs[w];
        orow[D] = (p1h * t + p2h) / (t + 1.0f);
    }
}

// ---------------- launch --------------------------------------------------------
extern "C" void kernel_launch(void* const* d_in, const int* in_sizes, int n_in,
                              void* d_out, int out_size) {
    const float* x  = (const float*)d_in[0];
    const float* Ws = (const float*)d_in[1];
    const float* Wn = (const float*)d_in[2];
    const int*   ei = (const int*)d_in[3];
    int N = in_sizes[0] / (D + 1);
    if (N > NMAX) N = NMAX;
    int E = in_sizes[3] / 2;
    if (E > EMAX) E = EMAX;
    float* out = (float*)d_out;

    cudaFuncSetAttribute(gemm_wmma_kernel, cudaFuncAttributeMaxDynamicSharedMemorySize,
                         GEMM_SMEM);

    // Side stream + fork/join events: created ONCE on the first call (the
    // correctness run, which is not capturing). The capture call then performs
    // only capture-legal ops on them (event record / stream wait = graph nodes).
    // Never destroyed (destroying a forked stream mid-capture invalidates the
    // capture). Identical GPU work is issued on every call.
    static cudaStream_t s2 = nullptr;
    static cudaEvent_t evF = nullptr, evJ = nullptr;
    if (s2 == nullptr) {
        cudaStreamCreateWithFlags(&s2, cudaStreamNonBlocking);
        cudaEventCreateWithFlags(&evF, cudaEventDisableTiming);
        cudaEventCreateWithFlags(&evJ, cudaEventDisableTiming);
    }

    int warpBlocks = (N * 32 + 255) / 256;
    int wsplitBlocks = (NC * D + 255) / 256;
    int NB = (N + 255) / 256;
    int EB = (E + 255) / 256;

    // Fork: edge-bucketing chain runs concurrently with the compute chain.
    cudaEventRecord(evF, (cudaStream_t)0);
    cudaStreamWaitEvent(s2, evF, 0);
    zerodeg_kernel<<<NB, 256, 0, s2>>>(N);
    count_kernel<<<EB, 256, 0, s2>>>(ei, E);
    scan1_kernel<<<NB, 256, 0, s2>>>(N);
    scan2_kernel<<<1, 160, 0, s2>>>(NB, N);
    scan3_kernel<<<NB, 256, 0, s2>>>(N);
    fill_kernel<<<EB, 256, 0, s2>>>(ei, E);
    cudaEventRecord(evJ, s2);

    // Compute chain on the default (captured) stream.
    prep_wsplit_kernel<<<warpBlocks + wsplitBlocks, 256>>>(x, Ws, Wn, N, warpBlocks);
    dim3 gg((N + 127) / 128, NC / 128);
    gemm_wmma_kernel<<<gg, 256, GEMM_SMEM>>>(N);
    norm_kernel<<<(2 * N * 32 + 255) / 256, 256>>>(2 * N);

    // Join, then aggregate.
    cudaStreamWaitEvent((cudaStream_t)0, evJ, 0);
    agg_kernel<<<warpBlocks, 256>>>(out, N);
}

// round 16
// speedup vs baseline: 2.0666x; 1.0034x over previous
#include <cuda_runtime.h>
#include <cuda_bf16.h>
#include <cuda_fp16.h>
#include <mma.h>
#include <cstdint>

using namespace nvcuda;

#define NMAX 20000
#define XPAD 20096           // NMAX rounded up to 128-row tiles
#define EMAX 320000
#define D 256
#define NC 512   // self 256 cols | neigh 256 cols

// ---------------- scratch (__device__ globals) ----------------------------------
__device__ __align__(16) __nv_bfloat16 g_Xhi[(size_t)XPAD * D];
__device__ __align__(16) __nv_bfloat16 g_Xlo[(size_t)XPAD * D];
__device__ __align__(16) __nv_bfloat16 g_Whi[NC * D];   // [n][k], K-major
__device__ __align__(16) __nv_bfloat16 g_Wlo[NC * D];
__device__ __align__(16) float g_C[(size_t)(XPAD + 128) * NC];  // raw GEMM out
__device__ __align__(16) __half g_Nh[(size_t)NMAX * D];         // normalized neigh half, fp16
__device__ __align__(16) float2 g_sinv[NMAX];                   // (inv, off) for self half
__device__ float g_habs[NMAX];
__device__ int g_deg[NMAX];     // zero-initialized at load; agg re-zeroes each call
__device__ int g_off[NMAX + 1];
__device__ int g_cur[NMAX];
__device__ int g_bucket[EMAX];
__device__ int g_bsum[160];
__device__ int g_bpre[160];

__device__ __forceinline__ float warp_sum(float v) {
#pragma unroll
    for (int o = 16; o > 0; o >>= 1) v += __shfl_xor_sync(0xffffffffu, v, o);
    return v;
}
__device__ __forceinline__ uint32_t smem_u32(const void* p) {
    uint32_t a;
    asm("{ .reg .u64 t; cvta.to.shared.u64 t, %1; cvt.u32.u64 %0, t; }" : "=r"(a) : "l"(p));
    return a;
}
#define CP_ASYNC16(dst, src) \
    asm volatile("cp.async.cg.shared.global [%0], [%1], 16;" :: "r"(dst), "l"(src))
#define CP_COMMIT() asm volatile("cp.async.commit_group;" ::: "memory")
#define CP_WAIT(n)  asm volatile("cp.async.wait_group %0;" :: "n"(n) : "memory")

// ---------------- 1. fused: per-node normalize+split  |  W concat+split ---------
__global__ void prep_wsplit_kernel(const float* __restrict__ x,
                                   const float* __restrict__ Ws,
                                   const float* __restrict__ Wn,
                                   int N, int PB) {
    if (blockIdx.x < PB) {
        // ---- prep part ----
        int gid = blockIdx.x * blockDim.x + threadIdx.x;
        int w = gid >> 5;
        int lane = threadIdx.x & 31;
        if (w >= N) return;
        const float* xr = x + (size_t)w * (D + 1);
        float v[8];
        float ss = 0.f;
        bool nz = false;
#pragma unroll
        for (int k = 0; k < 8; k++) {
            float t = xr[k * 32 + lane];
            v[k] = t; ss += t * t; nz |= (t != 0.f);
        }
        unsigned m = __ballot_sync(0xffffffffu, nz);
        ss = warp_sum(ss);
        float h = xr[D];
        float s0 = (h < 0.f) ? -1.f : 1.f;
        float scale;
        if (m == 0u) {
#pragma unroll
            for (int k = 0; k < 8; k++) v[k] = 1.f;
            scale = s0 * (1.f / 16.f);
        } else {
            scale = s0 / fmaxf(sqrtf(ss), 1e-8f);
        }
#pragma unroll
        for (int k = 0; k < 8; k++) {
            float val = v[k] * scale;
            __nv_bfloat16 hi = __float2bfloat16_rn(val);
            float lo = val - __bfloat162float(hi);
            size_t idx = (size_t)w * D + k * 32 + lane;
            g_Xhi[idx] = hi;
            g_Xlo[idx] = __float2bfloat16_rn(lo);
        }
        if (lane == 0) g_habs[w] = h * s0;
    } else {
        // ---- wsplit part ----
        int idx = (blockIdx.x - PB) * blockDim.x + threadIdx.x;
        if (idx >= NC * D) return;
        int j = idx / D, k = idx % D;
        float w = (j < D) ? Ws[j * D + k] : Wn[(j - D) * D + k];
        __nv_bfloat16 hi = __float2bfloat16_rn(w);
        g_Whi[idx] = hi;
        g_Wlo[idx] = __float2bfloat16_rn(w - __bfloat162float(hi));
    }
}

// ---------------- 2. count edges per destination (g_deg zeroed by prior agg) ----
__global__ void count_kernel(const int* __restrict__ ei, int E) {
    int e = blockIdx.x * blockDim.x + threadIdx.x;
    if (e < E) atomicAdd(&g_deg[ei[e]], 1);
}

// ---------------- 3a/b/c. parallel exclusive scan -------------------------------
__global__ void scan1_kernel(int N) {
    __shared__ int sh[256];
    int t = threadIdx.x;
    int i = blockIdx.x * 256 + t;
    sh[t] = (i < N) ? g_deg[i] : 0;
    __syncthreads();
#pragma unroll
    for (int o = 128; o > 0; o >>= 1) {
        if (t < o) sh[t] += sh[t + o];
        __syncthreads();
    }
    if (t == 0) g_bsum[blockIdx.x] = sh[0];
}
__global__ void scan2_kernel(int NB, int N) {
    __shared__ int sh[160];
    int t = threadIdx.x;
    int v = (t < NB) ? g_bsum[t] : 0;
    sh[t] = v;
    __syncthreads();
    for (int o = 1; o < 160; o <<= 1) {
        int u = (t >= o) ? sh[t - o] : 0;
        __syncthreads();
        sh[t] += u;
        __syncthreads();
    }
    if (t < NB) g_bpre[t] = sh[t] - v;
    if (t == NB - 1) g_off[N] = sh[t];
}
__global__ void scan3_kernel(int N) {
    __shared__ int sh[256];
    int t = threadIdx.x;
    int i = blockIdx.x * 256 + t;
    int v = (i < N) ? g_deg[i] : 0;
    sh[t] = v;
    __syncthreads();
#pragma unroll
    for (int o = 1; o < 256; o <<= 1) {
        int u = (t >= o) ? sh[t - o] : 0;
        __syncthreads();
        sh[t] += u;
        __syncthreads();
    }
    if (i < N) {
        int e = sh[t] - v + g_bpre[blockIdx.x];
        g_off[i] = e;
        g_cur[i] = e;
    }
}

// ---------------- 4. bucket edge sources by destination -------------------------
__global__ void fill_kernel(const int* __restrict__ ei, int E) {
    int e = blockIdx.x * blockDim.x + threadIdx.x;
    if (e < E) {
        int r = ei[e];
        int c = ei[E + e];
        int p = atomicAdd(&g_cur[r], 1);
        g_bucket[p] = c;
    }
}

// ---------------- 5. WMMA bf16 3-term GEMM, 3-stage cp.async pipeline -----------
// One __syncthreads per K-chunk; prefetch distance 2 overlaps a full MMA chunk.
#define GLDM 40
#define STAGE_ARR (128 * GLDM * 2)        // bytes per array (10240)
#define STAGE_BYTES (4 * STAGE_ARR)       // AsHi|AsLo|BsHi|BsLo (40960)
#define GEMM_SMEM (3 * STAGE_BYTES)       // 122880

__device__ __forceinline__ void gemm_stage_load(char* smem, int s, int row0, int j0,
                                                int kc, int tid) {
    char* base = smem + s * STAGE_BYTES;
    uint32_t uAhi = smem_u32(base);
    uint32_t uAlo = uAhi + STAGE_ARR;
    uint32_t uBhi = uAhi + 2 * STAGE_ARR;
    uint32_t uBlo = uAhi + 3 * STAGE_ARR;
#pragma unroll
    for (int t = 0; t < 2; t++) {
        int o = tid + t * 256;            // 0..511
        int row = o >> 2;                 // 0..127
        int seg = o & 3;                  // 16B segment
        uint32_t doff = row * 80 + seg * 16;
        size_t aoff = (size_t)(row0 + row) * D + kc + seg * 8;  // 8 bf16 = 16B
        size_t boff = (size_t)(j0 + row) * D + kc + seg * 8;
        CP_ASYNC16(uAhi + doff, (const char*)(g_Xhi + aoff));
        CP_ASYNC16(uAlo + doff, (const char*)(g_Xlo + aoff));
        CP_ASYNC16(uBhi + doff, (const char*)(g_Whi + boff));
        CP_ASYNC16(uBlo + doff, (const char*)(g_Wlo + boff));
    }
}

__global__ __launch_bounds__(256) void gemm_wmma_kernel(int M) {
    extern __shared__ char smem[];
    int tid = threadIdx.x;
    int wid = tid >> 5;
    int warp_row = wid >> 2;      // 0..1
    int warp_col = wid & 3;       // 0..3
    int row0 = blockIdx.x * 128;
    int j0 = blockIdx.y * 128;

    wmma::fragment<wmma::accumulator, 16, 16, 16, float> acc[4][2];
#pragma unroll
    for (int i = 0; i < 4; i++)
#pragma unroll
        for (int j = 0; j < 2; j++) wmma::fill_fragment(acc[i][j], 0.f);

    gemm_stage_load(smem, 0, row0, j0, 0, tid);
    CP_COMMIT();
    gemm_stage_load(smem, 1, row0, j0, 32, tid);
    CP_COMMIT();

#pragma unroll
    for (int c = 0; c < 8; c++) {
        int s = c % 3;
        if (c < 7) { CP_WAIT(1); } else { CP_WAIT(0); }
        // Single barrier: makes chunk-c data visible to all warps AND ensures
        // every warp finished the MMA of chunk c-1 (whose buffer (c+2)%3 is
        // about to be overwritten by the prefetch below).
        __syncthreads();
        if (c + 2 < 8) {
            gemm_stage_load(smem, (c + 2) % 3, row0, j0, (c + 2) * 32, tid);
            CP_COMMIT();
        }

        const __nv_bfloat16* AsHi = (const __nv_bfloat16*)(smem + s * STAGE_BYTES);
        const __nv_bfloat16* BsHi = AsHi + 2 * 128 * GLDM;
#pragma unroll
        for (int ks = 0; ks < 2; ks++) {
            wmma::fragment<wmma::matrix_a, 16, 16, 16, __nv_bfloat16, wmma::row_major> aHi[4], aLo[4];
            wmma::fragment<wmma::matrix_b, 16, 16, 16, __nv_bfloat16, wmma::col_major> bHi[2], bLo[2];
#pragma unroll
            for (int i = 0; i < 4; i++) {
                const __nv_bfloat16* pa = AsHi + (warp_row * 64 + i * 16) * GLDM + ks * 16;
                wmma::load_matrix_sync(aHi[i], pa, GLDM);
                wmma::load_matrix_sync(aLo[i], pa + 128 * GLDM, GLDM);
            }
#pragma unroll
            for (int j = 0; j < 2; j++) {
                const __nv_bfloat16* pb = BsHi + (warp_col * 32 + j * 16) * GLDM + ks * 16;
                wmma::load_matrix_sync(bHi[j], pb, GLDM);
                wmma::load_matrix_sync(bLo[j], pb + 128 * GLDM, GLDM);
            }
#pragma unroll
            for (int i = 0; i < 4; i++)
#pragma unroll
                for (int j = 0; j < 2; j++) {
                    wmma::mma_sync(acc[i][j], aHi[i], bHi[j], acc[i][j]);
                    wmma::mma_sync(acc[i][j], aHi[i], bLo[j], acc[i][j]);
                    wmma::mma_sync(acc[i][j], aLo[i], bHi[j], acc[i][j]);
                }
        }
    }

#pragma unroll
    for (int i = 0; i < 4; i++) {
        int r = row0 + warp_row * 64 + i * 16;
#pragma unroll
        for (int j = 0; j < 2; j++) {
            float* cp = g_C + (size_t)r * NC + j0 + warp_col * 32 + j * 16;
            wmma::store_matrix_sync(cp, acc[i][j], NC, wmma::mem_row_major);
        }
    }
}

// ---------------- 6. per-half-row: self -> (inv,off); neigh -> fp16 row ---------
__global__ void norm_kernel(int N2) {
    int w = (blockIdx.x * blockDim.x + threadIdx.x) >> 5;
    int lane = threadIdx.x & 31;
    if (w >= N2) return;
    const float* p = g_C + (size_t)w * D;   // half-row w (NC = 2*D)
    float v[8];
    float ss = 0.f;
#pragma unroll
    for (int k = 0; k < 8; k++) {
        float t = p[k * 32 + lane];
        v[k] = t;
        ss += t * t;
    }
    ss = warp_sum(ss);
    int node = w >> 1;
    if ((w & 1) == 0) {
        if (lane == 0)
            g_sinv[node] = (ss == 0.f) ? make_float2(0.f, 0.0625f)
                                       : make_float2(1.f / fmaxf(sqrtf(ss), 1e-8f), 0.f);
    } else {
        __half* q = g_Nh + (size_t)node * D;
        if (ss == 0.f) {
            __half c = __float2half(0.0625f);
#pragma unroll
            for (int k = 0; k < 8; k++) q[k * 32 + lane] = c;
        } else {
            float inv = 1.f / fmaxf(sqrtf(ss), 1e-8f);
#pragma unroll
            for (int k = 0; k < 8; k++) q[k * 32 + lane] = __float2half(v[k] * inv);
        }
    }
}

// ---------------- 7. aggregation + blend + final normalize (1 warp / node) ------
__global__ void agg_kernel(float* __restrict__ out, int N) {
    int w = (blockIdx.x * blockDim.x + threadIdx.x) >> 5;
    int lane = threadIdx.x & 31;
    if (w >= N) return;
    int beg = g_off[w], end = g_off[w + 1];
    float accx[4] = {0.f, 0.f, 0.f, 0.f};
    float accy[4] = {0.f, 0.f, 0.f, 0.f};
    float acch = 0.f;
    const __half2* nh = (const __half2*)g_Nh;
    for (int e = beg; e < end; e++) {
        int c = g_bucket[e];
        const __half2* p = nh + (size_t)c * (D / 2);
#pragma unroll
        for (int k = 0; k < 4; k++) {
            float2 f = __half22float2(p[k * 32 + lane]);
            accx[k] += f.x;
            accy[k] += f.y;
        }
        acch += g_habs[c];
    }
    float ss = 0.f;
#pragma unroll
    for (int k = 0; k < 4; k++) ss += accx[k] * accx[k] + accy[k] * accy[k];
    ss = warp_sum(ss);
    float p2x[4], p2y[4];
    if (ss == 0.f) {
#pragma unroll
        for (int k = 0; k < 4; k++) { p2x[k] = 0.0625f; p2y[k] = 0.0625f; }
    } else {
        float iv = 1.f / fmaxf(sqrtf(ss), 1e-8f);
#pragma unroll
        for (int k = 0; k < 4; k++) { p2x[k] = accx[k] * iv; p2y[k] = accy[k] * iv; }
    }
    float p2h = 1.f + acch;
    const float t = 0.5f / (1.0f - 0.5f + 1e-8f);  // == 1.0f in fp32, as reference
    float2 si = g_sinv[w];                          // (inv, off)
    const float2* srow2 = (const float2*)(g_C + (size_t)w * NC);
    float avx[4], avy[4];
    float ss2 = 0.f;
#pragma unroll
    for (int k = 0; k < 4; k++) {
        float2 s = srow2[k * 32 + lane];
        float ax = (s.x * si.x + si.y) * t + p2x[k];
        float ay = (s.y * si.x + si.y) * t + p2y[k];
        avx[k] = ax; avy[k] = ay;
        ss2 += ax * ax + ay * ay;
    }
    ss2 = warp_sum(ss2);
    float* orow = out + (size_t)w * (D + 1);
    if (ss2 == 0.f) {
#pragma unroll
        for (int k = 0; k < 4; k++) {
            int j = 2 * (k * 32 + lane);
            orow[j] = 0.0625f;
            orow[j + 1] = 0.0625f;
        }
    } else {
        float iv = 1.f / fmaxf(sqrtf(ss2), 1e-8f);
#pragma unroll
        for (int k = 0; k < 4; k++) {
            int j = 2 * (k * 32 + lane);
            orow[j] = avx[k] * iv;
            orow[j + 1] = avy[k] * iv;
        }
    }
    if (lane == 0) {
        float p1h = g_habs[w];
        orow[D] = (p1h * t + p2h) / (t + 1.0f);
        g_deg[w] = 0;   // reset for the next call's count_kernel
    }
}

// ---------------- launch --------------------------------------------------------
extern "C" void kernel_launch(void* const* d_in, const int* in_sizes, int n_in,
                              void* d_out, int out_size) {
    const float* x  = (const float*)d_in[0];
    const float* Ws = (const float*)d_in[1];
    const float* Wn = (const float*)d_in[2];
    const int*   ei = (const int*)d_in[3];
    int N = in_sizes[0] / (D + 1);
    if (N > NMAX) N = NMAX;
    int E = in_sizes[3] / 2;
    if (E > EMAX) E = EMAX;
    float* out = (float*)d_out;

    cudaFuncSetAttribute(gemm_wmma_kernel, cudaFuncAttributeMaxDynamicSharedMemorySize,
                         GEMM_SMEM);

    // Side stream + fork/join events: created ONCE on the first (non-capturing)
    // call; never destroyed. Capture calls only record/wait events on them.
    static cudaStream_t s2 = nullptr;
    static cudaEvent_t evF = nullptr, evJ = nullptr;
    if (s2 == nullptr) {
        cudaStreamCreateWithFlags(&s2, cudaStreamNonBlocking);
        cudaEventCreateWithFlags(&evF, cudaEventDisableTiming);
        cudaEventCreateWithFlags(&evJ, cudaEventDisableTiming);
    }

    int warpBlocks = (N * 32 + 255) / 256;
    int wsplitBlocks = (NC * D + 255) / 256;
    int NB = (N + 255) / 256;
    int EB = (E + 255) / 256;

    // Fork: edge-bucketing chain runs concurrently with the compute chain.
    cudaEventRecord(evF, (cudaStream_t)0);
    cudaStreamWaitEvent(s2, evF, 0);
    count_kernel<<<EB, 256, 0, s2>>>(ei, E);
    scan1_kernel<<<NB, 256, 0, s2>>>(N);
    scan2_kernel<<<1, 160, 0, s2>>>(NB, N);
    scan3_kernel<<<NB, 256, 0, s2>>>(N);
    fill_kernel<<<EB, 256, 0, s2>>>(ei, E);
    cudaEventRecord(evJ, s2);

    // Compute chain on the default (captured) stream.
    prep_wsplit_kernel<<<warpBlocks + wsplitBlocks, 256>>>(x, Ws, Wn, N, warpBlocks);
    dim3 gg((N + 127) / 128, NC / 128);
    gemm_wmma_kernel<<<gg, 256, GEMM_SMEM>>>(N);
    norm_kernel<<<(2 * N * 32 + 255) / 256, 256>>>(2 * N);

    // Join, then aggregate.
    cudaStreamWaitEvent((cudaStream_t)0, evJ, 0);
    agg_kernel<<<warpBlocks, 256>>>(out, N);
}